// round 1
// baseline (speedup 1.0000x reference)
#include <cuda_runtime.h>
#include <cstdint>

#define NTOT 1000000
#define N0C  495616
#define N1C  45056
#define N2C  4096
#define E0C  450560
#define E1C  40960
#define DC   128
#define PC   4096

// ---------------- device scratch (static, allocation-free) ----------------
__device__ float g_mean0[N1C * DC];
__device__ float g_h1[N1C * DC];
__device__ float g_mean1[N2C * DC];
__device__ float g_h2[N2C * DC];
__device__ int   g_hist0[N1C];
__device__ int   g_off0[N1C + 1];
__device__ int   g_cur0[N1C];
__device__ int   g_hist1[N2C];
__device__ int   g_off1[N2C + 1];
__device__ int   g_cur1[N2C];
__device__ int   g_sorted0[E0C];
__device__ int   g_sorted1[E1C];

// ---------------- CSR build ----------------
__global__ void zero_k() {
    int i = blockIdx.x * blockDim.x + threadIdx.x;
    if (i < N1C) g_hist0[i] = 0;
    if (i < N2C) g_hist1[i] = 0;
}

__device__ __forceinline__ void hist_body(const int* __restrict__ edst, int E, int* hist) {
    int e = blockIdx.x * blockDim.x + threadIdx.x;
    if (e < E) atomicAdd(&hist[edst[e]], 1);
}
__global__ void hist0_k(const int* __restrict__ edst) { hist_body(edst, E0C, g_hist0); }
__global__ void hist1_k(const int* __restrict__ edst) { hist_body(edst, E1C, g_hist1); }

__device__ __forceinline__ void scan_body(const int* __restrict__ hist, int n,
                                          int* __restrict__ offs, int* __restrict__ cur) {
    __shared__ int partial[1024];
    int tid = threadIdx.x;
    int per = (n + 1023) >> 10;
    int start = tid * per;
    int end = start + per; if (end > n) end = n;
    int s = 0;
    for (int i = start; i < end; i++) s += hist[i];
    partial[tid] = s;
    __syncthreads();
    for (int d = 1; d < 1024; d <<= 1) {
        int v = (tid >= d) ? partial[tid - d] : 0;
        __syncthreads();
        partial[tid] += v;
        __syncthreads();
    }
    int run = (tid == 0) ? 0 : partial[tid - 1];
    for (int i = start; i < end; i++) {
        offs[i] = run; cur[i] = run;
        run += hist[i];
    }
    if (tid == 1023) offs[n] = run;
}
__global__ void scan0_k() { scan_body(g_hist0, N1C, g_off0, g_cur0); }
__global__ void scan1_k() { scan_body(g_hist1, N2C, g_off1, g_cur1); }

__device__ __forceinline__ void scatter_body(const int* __restrict__ esrc, const int* __restrict__ edst,
                                             const int* __restrict__ inode, int E,
                                             int* cur, int* __restrict__ sorted) {
    int e = blockIdx.x * blockDim.x + threadIdx.x;
    if (e >= E) return;
    int d = edst[e];
    int p = atomicAdd(&cur[d], 1);
    int s = esrc[e];
    sorted[p] = inode ? inode[s] : s;
}
__global__ void scat0_k(const int* __restrict__ esrc, const int* __restrict__ edst,
                        const int* __restrict__ inode) {
    scatter_body(esrc, edst, inode, E0C, g_cur0, g_sorted0);
}
__global__ void scat1_k(const int* __restrict__ esrc, const int* __restrict__ edst) {
    scatter_body(esrc, edst, nullptr, E1C, g_cur1, g_sorted1);
}

// ---------------- neighbor mean aggregation: one warp per dst ----------------
__device__ __forceinline__ void agg_body(const float* __restrict__ feat,
                                         const int* __restrict__ offs,
                                         const int* __restrict__ sorted,
                                         int n_dst, float* __restrict__ mean_out) {
    int w = (int)((blockIdx.x * (long)blockDim.x + threadIdx.x) >> 5);
    int lane = threadIdx.x & 31;
    if (w >= n_dst) return;
    int beg = offs[w], end = offs[w + 1];
    const float4* f4 = (const float4*)feat;
    float4 acc = make_float4(0.f, 0.f, 0.f, 0.f);
    for (int j = beg; j < end; j++) {
        long r = sorted[j];
        float4 v = f4[r * 32 + lane];
        acc.x += v.x; acc.y += v.y; acc.z += v.z; acc.w += v.w;
    }
    float deg = (float)(end - beg);
    float sc = 1.0f / fmaxf(deg, 1.0f);
    ((float4*)mean_out)[(long)w * 32 + lane] =
        make_float4(acc.x * sc, acc.y * sc, acc.z * sc, acc.w * sc);
}
__global__ void agg0_k(const float* __restrict__ nf) { agg_body(nf, g_off0, g_sorted0, N1C, g_mean0); }
__global__ void agg1_k() { agg_body(g_h1, g_off1, g_sorted1, N2C, g_mean1); }

// ---------------- fused dual-A GEMM (fp32, f32x2 packed FMA) ----------------
// C[m][n] = Aself[m] @ Ws + Aneigh[m] @ Wn + b   (+ optional relu)
// LAYER 0: M=45056, self rows gathered via input_nodes from node_features, relu.
// LAYER 1: M=4096,  self rows = g_h1 directly, no relu.
template <int LAYER>
__global__ void __launch_bounds__(256) gemm_k(const float* __restrict__ nf,
                                              const int* __restrict__ inode,
                                              const float* __restrict__ Ws,
                                              const float* __restrict__ Wn,
                                              const float* __restrict__ bias) {
    constexpr int ROWS = (LAYER == 0) ? 64 : 32;
    constexpr bool RELU = (LAYER == 0);
    constexpr int RPT = ROWS / 16;           // rows per thread: 4 or 2
    const float* __restrict__ Aneigh = (LAYER == 0) ? g_mean0 : g_mean1;
    const float* __restrict__ AselfB = (LAYER == 0) ? nf : g_h1;
    float* __restrict__ outp = (LAYER == 0) ? g_h1 : g_h2;

    extern __shared__ float sm[];
    float* sWs = sm;                         // 128*128
    float* sWn = sm + 16384;                 // 128*128
    float* sAs = sm + 32768;                 // 32*ROWS (k-major, transposed)
    float* sAn = sAs + 32 * ROWS;            // 32*ROWS

    int tid = threadIdx.x;
    int m0 = blockIdx.x * ROWS;

    // cooperative load of both weight matrices into smem
    {
        float4* dWs = (float4*)sWs; const float4* gWs = (const float4*)Ws;
        float4* dWn = (float4*)sWn; const float4* gWn = (const float4*)Wn;
#pragma unroll 4
        for (int i = tid; i < 4096; i += 256) { dWs[i] = gWs[i]; dWn[i] = gWn[i]; }
    }

    constexpr int TPR = 256 / ROWS;          // threads per row: 4 or 8
    constexpr int KW  = 32 / TPR;            // k-floats per thread: 8 or 4
    constexpr int NF4 = KW / 4;              // float4s per thread: 2 or 1
    int li  = tid / TPR;                     // row in tile for loading
    int lks = (tid % TPR) * KW;              // k offset within chunk

    int tx = tid & 15;                       // col-pair group: pairs at n = 2*tx + 32*j
    int ty = tid >> 4;
    int i0 = ty * RPT;

    unsigned long long acc[RPT][4];
#pragma unroll
    for (int r = 0; r < RPT; r++)
#pragma unroll
        for (int j = 0; j < 4; j++) acc[r][j] = 0ull;

    long selfRow;
    if (LAYER == 0) selfRow = (long)inode[m0 + li];
    else            selfRow = (long)(m0 + li);
    long neighRow = (long)(m0 + li);

#pragma unroll 1
    for (int kc = 0; kc < 4; kc++) {
        __syncthreads();   // prior chunk's compute done (and W load on first iter)
        const float4* srcS = (const float4*)(AselfB + selfRow * 128 + kc * 32 + lks);
        const float4* srcN = (const float4*)(Aneigh + neighRow * 128 + kc * 32 + lks);
#pragma unroll
        for (int q = 0; q < NF4; q++) {
            float4 vs = srcS[q];
            float4 vn = srcN[q];
            int kq = lks + q * 4;
            sAs[(kq + 0) * ROWS + li] = vs.x; sAs[(kq + 1) * ROWS + li] = vs.y;
            sAs[(kq + 2) * ROWS + li] = vs.z; sAs[(kq + 3) * ROWS + li] = vs.w;
            sAn[(kq + 0) * ROWS + li] = vn.x; sAn[(kq + 1) * ROWS + li] = vn.y;
            sAn[(kq + 2) * ROWS + li] = vn.z; sAn[(kq + 3) * ROWS + li] = vn.w;
        }
        __syncthreads();

        const float* wS = sWs + (kc * 32) * 128 + 2 * tx;
        const float* wN = sWn + (kc * 32) * 128 + 2 * tx;
#pragma unroll 8
        for (int kk = 0; kk < 32; kk++) {
            unsigned long long ws0 = *(const unsigned long long*)(wS + kk * 128 + 0);
            unsigned long long ws1 = *(const unsigned long long*)(wS + kk * 128 + 32);
            unsigned long long ws2 = *(const unsigned long long*)(wS + kk * 128 + 64);
            unsigned long long ws3 = *(const unsigned long long*)(wS + kk * 128 + 96);
            unsigned long long wn0 = *(const unsigned long long*)(wN + kk * 128 + 0);
            unsigned long long wn1 = *(const unsigned long long*)(wN + kk * 128 + 32);
            unsigned long long wn2 = *(const unsigned long long*)(wN + kk * 128 + 64);
            unsigned long long wn3 = *(const unsigned long long*)(wN + kk * 128 + 96);

            float as[RPT], an[RPT];
            if constexpr (RPT == 4) {
                float4 a = *(const float4*)&sAs[kk * ROWS + i0];
                float4 b = *(const float4*)&sAn[kk * ROWS + i0];
                as[0] = a.x; as[1] = a.y; as[2] = a.z; as[3] = a.w;
                an[0] = b.x; an[1] = b.y; an[2] = b.z; an[3] = b.w;
            } else {
                float2 a = *(const float2*)&sAs[kk * ROWS + i0];
                float2 b = *(const float2*)&sAn[kk * ROWS + i0];
                as[0] = a.x; as[1] = a.y;
                an[0] = b.x; an[1] = b.y;
            }
#pragma unroll
            for (int r = 0; r < RPT; r++) {
                unsigned long long ap, np;
                asm("mov.b64 %0, {%1, %1};" : "=l"(ap) : "f"(as[r]));
                asm("mov.b64 %0, {%1, %1};" : "=l"(np) : "f"(an[r]));
                asm("fma.rn.f32x2 %0, %1, %2, %0;" : "+l"(acc[r][0]) : "l"(ap), "l"(ws0));
                asm("fma.rn.f32x2 %0, %1, %2, %0;" : "+l"(acc[r][1]) : "l"(ap), "l"(ws1));
                asm("fma.rn.f32x2 %0, %1, %2, %0;" : "+l"(acc[r][2]) : "l"(ap), "l"(ws2));
                asm("fma.rn.f32x2 %0, %1, %2, %0;" : "+l"(acc[r][3]) : "l"(ap), "l"(ws3));
                asm("fma.rn.f32x2 %0, %1, %2, %0;" : "+l"(acc[r][0]) : "l"(np), "l"(wn0));
                asm("fma.rn.f32x2 %0, %1, %2, %0;" : "+l"(acc[r][1]) : "l"(np), "l"(wn1));
                asm("fma.rn.f32x2 %0, %1, %2, %0;" : "+l"(acc[r][2]) : "l"(np), "l"(wn2));
                asm("fma.rn.f32x2 %0, %1, %2, %0;" : "+l"(acc[r][3]) : "l"(np), "l"(wn3));
            }
        }
    }

    // epilogue: bias (+relu) + store pairs
#pragma unroll
    for (int r = 0; r < RPT; r++) {
        long row = (long)(m0 + i0 + r);
#pragma unroll
        for (int j = 0; j < 4; j++) {
            int n = 2 * tx + 32 * j;
            float lo, hi;
            asm("mov.b64 {%0, %1}, %2;" : "=f"(lo), "=f"(hi) : "l"(acc[r][j]));
            lo += bias[n]; hi += bias[n + 1];
            if (RELU) { lo = fmaxf(lo, 0.f); hi = fmaxf(hi, 0.f); }
            float2 o; o.x = lo; o.y = hi;
            *(float2*)&outp[row * 128 + n] = o;
        }
    }
}

// ---------------- final pos/neg gathers ----------------
__global__ void out_k(const int* __restrict__ ps, const int* __restrict__ pd,
                      const int* __restrict__ ns, const int* __restrict__ nd,
                      float* __restrict__ out) {
    int w = (int)((blockIdx.x * (long)blockDim.x + threadIdx.x) >> 5);  // 0..16383
    int lane = threadIdx.x & 31;
    int grp = w >> 12;
    int r = w & (PC - 1);
    const int* tab = (grp == 0) ? ps : (grp == 1) ? pd : (grp == 2) ? ns : nd;
    long src = tab[r];
    float4 v = ((const float4*)g_h2)[src * 32 + lane];
    ((float4*)out)[(long)w * 32 + lane] = v;
}

// ---------------- launch ----------------
static const int SMEM0 = (16384 * 2 + 2 * 32 * 64) * 4;  // 147456 B
static const int SMEM1 = (16384 * 2 + 2 * 32 * 32) * 4;  // 139264 B

extern "C" void kernel_launch(void* const* d_in, const int* in_sizes, int n_in,
                              void* d_out, int out_size) {
    const float* nf    = (const float*)d_in[0];
    const int*   inode = (const int*)d_in[1];
    const int*   esrc0 = (const int*)d_in[2];
    const int*   edst0 = (const int*)d_in[3];
    const int*   esrc1 = (const int*)d_in[4];
    const int*   edst1 = (const int*)d_in[5];
    const int*   ps    = (const int*)d_in[6];
    const int*   pd    = (const int*)d_in[7];
    const int*   ns    = (const int*)d_in[8];
    const int*   nd    = (const int*)d_in[9];
    const float* Ws0   = (const float*)d_in[10];
    const float* Wn0   = (const float*)d_in[11];
    const float* b0    = (const float*)d_in[12];
    const float* Ws1   = (const float*)d_in[13];
    const float* Wn1   = (const float*)d_in[14];
    const float* b1    = (const float*)d_in[15];
    float* out = (float*)d_out;

    cudaFuncSetAttribute(reinterpret_cast<const void*>(gemm_k<0>),
                         cudaFuncAttributeMaxDynamicSharedMemorySize, SMEM0);
    cudaFuncSetAttribute(reinterpret_cast<const void*>(gemm_k<1>),
                         cudaFuncAttributeMaxDynamicSharedMemorySize, SMEM1);

    zero_k<<<176, 256>>>();
    hist0_k<<<(E0C + 255) / 256, 256>>>(edst0);
    hist1_k<<<(E1C + 255) / 256, 256>>>(edst1);
    scan0_k<<<1, 1024>>>();
    scan1_k<<<1, 1024>>>();
    scat0_k<<<(E0C + 255) / 256, 256>>>(esrc0, edst0, inode);
    scat1_k<<<(E1C + 255) / 256, 256>>>(esrc1, edst1);
    agg0_k<<<(N1C * 32 + 255) / 256, 256>>>(nf);
    gemm_k<0><<<N1C / 64, 256, SMEM0>>>(nf, inode, Ws0, Wn0, b0);
    agg1_k<<<(N2C * 32 + 255) / 256, 256>>>();
    gemm_k<1><<<N2C / 32, 256, SMEM1>>>(nf, inode, Ws1, Wn1, b1);
    out_k<<<(4 * PC * 32) / 256, 256>>>(ps, pd, ns, nd, out);
}

// round 3
// speedup vs baseline: 1.2992x; 1.2992x over previous
#include <cuda_runtime.h>
#include <cstdint>

#define NTOT 1000000
#define N0C  495616
#define N1C  45056
#define N2C  4096
#define E0C  450560
#define E1C  40960
#define DC   128
#define PC   4096

#define NB0  (N1C / 256)        // 176
#define NB1  (N2C / 256)        // 16
#define NBS  (NB0 + NB1)        // 192

// ---------------- device scratch (static, allocation-free) ----------------
__device__ float g_mean0[N1C * DC];
__device__ float g_h1[N1C * DC];
__device__ float g_mean1[N2C * DC];
__device__ float g_h2[N2C * DC];
__device__ int   g_hist0[N1C];
__device__ int   g_off0[N1C + 1];
__device__ int   g_cur0[N1C];
__device__ int   g_hist1[N2C];
__device__ int   g_off1[N2C + 1];
__device__ int   g_cur1[N2C];
__device__ int   g_sorted0[E0C];
__device__ int   g_sorted1[E1C];
__device__ int   g_part[NBS];
__device__ int   g_tot0, g_tot1;

// ---------------- fused histogram over both edge lists ----------------
__global__ void histF_k(const int* __restrict__ ed0, const int* __restrict__ ed1) {
    int e = blockIdx.x * 256 + threadIdx.x;
    if (e < E0C) atomicAdd(&g_hist0[ed0[e]], 1);
    else         atomicAdd(&g_hist1[ed1[e - E0C]], 1);
}

// ---------------- 3-phase scan (both graphs fused) ----------------
__global__ void scanA_k() {
    __shared__ int red[256];
    int b = blockIdx.x, t = threadIdx.x;
    int v = (b < NB0) ? g_hist0[b * 256 + t] : g_hist1[(b - NB0) * 256 + t];
    red[t] = v; __syncthreads();
#pragma unroll
    for (int d = 128; d > 0; d >>= 1) {
        if (t < d) red[t] += red[t + d];
        __syncthreads();
    }
    if (t == 0) g_part[b] = red[0];
}

__global__ void scanB_k() {       // 1 block, NBS threads
    __shared__ int s[NBS];
    int t = threadIdx.x;
    int v = g_part[t];
    s[t] = v; __syncthreads();
#pragma unroll
    for (int d = 1; d < NBS; d <<= 1) {
        int x = (t >= d) ? s[t - d] : 0;
        __syncthreads();
        s[t] += x;
        __syncthreads();
    }
    int tot0 = s[NB0 - 1];
    int excl = s[t] - v;
    if (t >= NB0) excl -= tot0;
    g_part[t] = excl;
    if (t == 0) { g_tot0 = tot0; g_tot1 = s[NBS - 1] - tot0; }
}

__global__ void scanC_k() {
    __shared__ int s[256];
    int b = blockIdx.x, t = threadIdx.x;
    bool is0 = (b < NB0);
    int i = is0 ? b * 256 + t : (b - NB0) * 256 + t;
    int v = is0 ? g_hist0[i] : g_hist1[i];
    s[t] = v; __syncthreads();
#pragma unroll
    for (int d = 1; d < 256; d <<= 1) {
        int x = (t >= d) ? s[t - d] : 0;
        __syncthreads();
        s[t] += x;
        __syncthreads();
    }
    int off = s[t] - v + g_part[b];
    if (is0) { g_off0[i] = off; g_cur0[i] = off; }
    else     { g_off1[i] = off; g_cur1[i] = off; }
    if (t == 255) {
        if (b == NB0 - 1) g_off0[N1C] = g_tot0;
        if (b == NBS - 1) g_off1[N2C] = g_tot1;
    }
}

// ---------------- fused scatter (counting-sort edge lists by dst) ----------------
__global__ void scatF_k(const int* __restrict__ es0, const int* __restrict__ ed0,
                        const int* __restrict__ es1, const int* __restrict__ ed1,
                        const int* __restrict__ inode) {
    int e = blockIdx.x * 256 + threadIdx.x;
    if (e < E0C) {
        int d = ed0[e];
        int p = atomicAdd(&g_cur0[d], 1);
        g_sorted0[p] = inode[es0[e]];
    } else {
        int k = e - E0C;
        int d = ed1[k];
        int p = atomicAdd(&g_cur1[d], 1);
        g_sorted1[p] = es1[k];
    }
}

// ---------------- neighbor mean aggregation: one warp per dst ----------------
__device__ __forceinline__ void agg_body(const float* __restrict__ feat,
                                         const int* __restrict__ offs,
                                         const int* __restrict__ sorted,
                                         int n_dst, float* __restrict__ mean_out) {
    int w = (int)((blockIdx.x * (long)blockDim.x + threadIdx.x) >> 5);
    int lane = threadIdx.x & 31;
    if (w >= n_dst) return;
    int beg = offs[w], end = offs[w + 1];
    const float4* f4 = (const float4*)feat;
    float4 acc = make_float4(0.f, 0.f, 0.f, 0.f);
    for (int j = beg; j < end; j++) {
        long r = sorted[j];
        float4 v = f4[r * 32 + lane];
        acc.x += v.x; acc.y += v.y; acc.z += v.z; acc.w += v.w;
    }
    float deg = (float)(end - beg);
    float sc = 1.0f / fmaxf(deg, 1.0f);
    ((float4*)mean_out)[(long)w * 32 + lane] =
        make_float4(acc.x * sc, acc.y * sc, acc.z * sc, acc.w * sc);
}
__global__ void agg0_k(const float* __restrict__ nf) { agg_body(nf, g_off0, g_sorted0, N1C, g_mean0); }
__global__ void agg1_k() { agg_body(g_h1, g_off1, g_sorted1, N2C, g_mean1); }

// ---------------- fused dual-A GEMM (fp32, f32x2 packed FMA) ----------------
template <int LAYER>
__global__ void __launch_bounds__(256) gemm_k(const float* __restrict__ nf,
                                              const int* __restrict__ inode,
                                              const float* __restrict__ Ws,
                                              const float* __restrict__ Wn,
                                              const float* __restrict__ bias) {
    constexpr int ROWS = (LAYER == 0) ? 64 : 32;
    constexpr bool RELU = (LAYER == 0);
    constexpr int RPT = ROWS / 16;           // rows per thread: 4 or 2
    const float* __restrict__ Aneigh = (LAYER == 0) ? g_mean0 : g_mean1;
    const float* __restrict__ AselfB = (LAYER == 0) ? nf : g_h1;
    float* __restrict__ outp = (LAYER == 0) ? g_h1 : g_h2;

    extern __shared__ float sm[];
    float* sWs = sm;                         // 128*128
    float* sWn = sm + 16384;                 // 128*128
    float* sAs = sm + 32768;                 // 32*ROWS (k-major, transposed)
    float* sAn = sAs + 32 * ROWS;            // 32*ROWS

    int tid = threadIdx.x;
    int m0 = blockIdx.x * ROWS;

    {
        float4* dWs = (float4*)sWs; const float4* gWs = (const float4*)Ws;
        float4* dWn = (float4*)sWn; const float4* gWn = (const float4*)Wn;
#pragma unroll 4
        for (int i = tid; i < 4096; i += 256) { dWs[i] = gWs[i]; dWn[i] = gWn[i]; }
    }

    constexpr int TPR = 256 / ROWS;          // threads per row: 4 or 8
    constexpr int KW  = 32 / TPR;            // k-floats per thread
    constexpr int NF4 = KW / 4;
    int li  = tid / TPR;
    int lks = (tid % TPR) * KW;

    int tx = tid & 15;
    int ty = tid >> 4;
    int i0 = ty * RPT;

    unsigned long long acc[RPT][4];
#pragma unroll
    for (int r = 0; r < RPT; r++)
#pragma unroll
        for (int j = 0; j < 4; j++) acc[r][j] = 0ull;

    long selfRow;
    if (LAYER == 0) selfRow = (long)inode[m0 + li];
    else            selfRow = (long)(m0 + li);
    long neighRow = (long)(m0 + li);

#pragma unroll 1
    for (int kc = 0; kc < 4; kc++) {
        __syncthreads();
        const float4* srcS = (const float4*)(AselfB + selfRow * 128 + kc * 32 + lks);
        const float4* srcN = (const float4*)(Aneigh + neighRow * 128 + kc * 32 + lks);
#pragma unroll
        for (int q = 0; q < NF4; q++) {
            float4 vs = srcS[q];
            float4 vn = srcN[q];
            int kq = lks + q * 4;
            sAs[(kq + 0) * ROWS + li] = vs.x; sAs[(kq + 1) * ROWS + li] = vs.y;
            sAs[(kq + 2) * ROWS + li] = vs.z; sAs[(kq + 3) * ROWS + li] = vs.w;
            sAn[(kq + 0) * ROWS + li] = vn.x; sAn[(kq + 1) * ROWS + li] = vn.y;
            sAn[(kq + 2) * ROWS + li] = vn.z; sAn[(kq + 3) * ROWS + li] = vn.w;
        }
        __syncthreads();

        const float* wS = sWs + (kc * 32) * 128 + 2 * tx;
        const float* wN = sWn + (kc * 32) * 128 + 2 * tx;
#pragma unroll 8
        for (int kk = 0; kk < 32; kk++) {
            unsigned long long ws0 = *(const unsigned long long*)(wS + kk * 128 + 0);
            unsigned long long ws1 = *(const unsigned long long*)(wS + kk * 128 + 32);
            unsigned long long ws2 = *(const unsigned long long*)(wS + kk * 128 + 64);
            unsigned long long ws3 = *(const unsigned long long*)(wS + kk * 128 + 96);
            unsigned long long wn0 = *(const unsigned long long*)(wN + kk * 128 + 0);
            unsigned long long wn1 = *(const unsigned long long*)(wN + kk * 128 + 32);
            unsigned long long wn2 = *(const unsigned long long*)(wN + kk * 128 + 64);
            unsigned long long wn3 = *(const unsigned long long*)(wN + kk * 128 + 96);

            float as[RPT], an[RPT];
            if constexpr (RPT == 4) {
                float4 a = *(const float4*)&sAs[kk * ROWS + i0];
                float4 b = *(const float4*)&sAn[kk * ROWS + i0];
                as[0] = a.x; as[1] = a.y; as[2] = a.z; as[3] = a.w;
                an[0] = b.x; an[1] = b.y; an[2] = b.z; an[3] = b.w;
            } else {
                float2 a = *(const float2*)&sAs[kk * ROWS + i0];
                float2 b = *(const float2*)&sAn[kk * ROWS + i0];
                as[0] = a.x; as[1] = a.y;
                an[0] = b.x; an[1] = b.y;
            }
#pragma unroll
            for (int r = 0; r < RPT; r++) {
                unsigned long long ap, np;
                asm("mov.b64 %0, {%1, %1};" : "=l"(ap) : "f"(as[r]));
                asm("mov.b64 %0, {%1, %1};" : "=l"(np) : "f"(an[r]));
                asm("fma.rn.f32x2 %0, %1, %2, %0;" : "+l"(acc[r][0]) : "l"(ap), "l"(ws0));
                asm("fma.rn.f32x2 %0, %1, %2, %0;" : "+l"(acc[r][1]) : "l"(ap), "l"(ws1));
                asm("fma.rn.f32x2 %0, %1, %2, %0;" : "+l"(acc[r][2]) : "l"(ap), "l"(ws2));
                asm("fma.rn.f32x2 %0, %1, %2, %0;" : "+l"(acc[r][3]) : "l"(ap), "l"(ws3));
                asm("fma.rn.f32x2 %0, %1, %2, %0;" : "+l"(acc[r][0]) : "l"(np), "l"(wn0));
                asm("fma.rn.f32x2 %0, %1, %2, %0;" : "+l"(acc[r][1]) : "l"(np), "l"(wn1));
                asm("fma.rn.f32x2 %0, %1, %2, %0;" : "+l"(acc[r][2]) : "l"(np), "l"(wn2));
                asm("fma.rn.f32x2 %0, %1, %2, %0;" : "+l"(acc[r][3]) : "l"(np), "l"(wn3));
            }
        }
    }

#pragma unroll
    for (int r = 0; r < RPT; r++) {
        long row = (long)(m0 + i0 + r);
#pragma unroll
        for (int j = 0; j < 4; j++) {
            int n = 2 * tx + 32 * j;
            float lo, hi;
            asm("mov.b64 {%0, %1}, %2;" : "=f"(lo), "=f"(hi) : "l"(acc[r][j]));
            lo += bias[n]; hi += bias[n + 1];
            if (RELU) { lo = fmaxf(lo, 0.f); hi = fmaxf(hi, 0.f); }
            float2 o; o.x = lo; o.y = hi;
            *(float2*)&outp[row * 128 + n] = o;
        }
    }
}

// ---------------- final pos/neg gathers ----------------
__global__ void out_k(const int* __restrict__ ps, const int* __restrict__ pd,
                      const int* __restrict__ ns, const int* __restrict__ nd,
                      float* __restrict__ out) {
    int w = (int)((blockIdx.x * (long)blockDim.x + threadIdx.x) >> 5);
    int lane = threadIdx.x & 31;
    int grp = w >> 12;
    int r = w & (PC - 1);
    const int* tab = (grp == 0) ? ps : (grp == 1) ? pd : (grp == 2) ? ns : nd;
    long src = tab[r];
    float4 v = ((const float4*)g_h2)[src * 32 + lane];
    ((float4*)out)[(long)w * 32 + lane] = v;
}

// ---------------- launch ----------------
static const int SMEM0 = (16384 * 2 + 2 * 32 * 64) * 4;  // 147456 B
static const int SMEM1 = (16384 * 2 + 2 * 32 * 32) * 4;  // 139264 B

extern "C" void kernel_launch(void* const* d_in, const int* in_sizes, int n_in,
                              void* d_out, int out_size) {
    const float* nf    = (const float*)d_in[0];
    const int*   inode = (const int*)d_in[1];
    const int*   esrc0 = (const int*)d_in[2];
    const int*   edst0 = (const int*)d_in[3];
    const int*   esrc1 = (const int*)d_in[4];
    const int*   edst1 = (const int*)d_in[5];
    const int*   ps    = (const int*)d_in[6];
    const int*   pd    = (const int*)d_in[7];
    const int*   ns    = (const int*)d_in[8];
    const int*   nd    = (const int*)d_in[9];
    const float* Ws0   = (const float*)d_in[10];
    const float* Wn0   = (const float*)d_in[11];
    const float* b0    = (const float*)d_in[12];
    const float* Ws1   = (const float*)d_in[13];
    const float* Wn1   = (const float*)d_in[14];
    const float* b1    = (const float*)d_in[15];
    float* out = (float*)d_out;

    cudaFuncSetAttribute(reinterpret_cast<const void*>(gemm_k<0>),
                         cudaFuncAttributeMaxDynamicSharedMemorySize, SMEM0);
    cudaFuncSetAttribute(reinterpret_cast<const void*>(gemm_k<1>),
                         cudaFuncAttributeMaxDynamicSharedMemorySize, SMEM1);

    void *p0 = nullptr, *p1 = nullptr;
    cudaGetSymbolAddress(&p0, g_hist0);
    cudaGetSymbolAddress(&p1, g_hist1);
    cudaMemsetAsync(p0, 0, N1C * sizeof(int));
    cudaMemsetAsync(p1, 0, N2C * sizeof(int));

    histF_k<<<(E0C + E1C) / 256, 256>>>(edst0, edst1);
    scanA_k<<<NBS, 256>>>();
    scanB_k<<<1, NBS>>>();
    scanC_k<<<NBS, 256>>>();
    scatF_k<<<(E0C + E1C) / 256, 256>>>(esrc0, edst0, esrc1, edst1, inode);
    agg0_k<<<(N1C * 32 + 255) / 256, 256>>>(nf);
    gemm_k<0><<<N1C / 64, 256, SMEM0>>>(nf, inode, Ws0, Wn0, b0);
    agg1_k<<<(N2C * 32 + 255) / 256, 256>>>();
    gemm_k<1><<<N2C / 32, 256, SMEM1>>>(nf, inode, Ws1, Wn1, b1);
    out_k<<<(4 * PC * 32) / 256, 256>>>(ps, pd, ns, nd, out);
}

// round 8
// speedup vs baseline: 1.4096x; 1.0850x over previous
#include <cuda_runtime.h>
#include <cuda_bf16.h>
#include <cstdint>

#define NTOT 1000000
#define N0C  495616
#define N1C  45056
#define N2C  4096
#define E0C  450560
#define E1C  40960
#define DC   128
#define PC   4096

#define NB0  (N1C / 256)        // 176
#define NB1  (N2C / 256)        // 16
#define NBS  (NB0 + NB1)        // 192

// ---------------- device scratch (static, allocation-free) ----------------
__device__ float g_mean0[N1C * DC];
__device__ float g_h1[N1C * DC];
__device__ float g_mean1[N2C * DC];
__device__ float g_h2[N2C * DC];
__device__ int   g_hist0[N1C];
__device__ int   g_off0[N1C + 1];
__device__ int   g_cur0[N1C];
__device__ int   g_hist1[N2C];
__device__ int   g_off1[N2C + 1];
__device__ int   g_cur1[N2C];
__device__ int   g_sorted0[E0C];
__device__ int   g_sorted1[E1C];
__device__ int   g_part[NBS];
__device__ int   g_tot0, g_tot1;

// ---------------- fused histogram over both edge lists ----------------
__global__ void histF_k(const int* __restrict__ ed0, const int* __restrict__ ed1) {
    int e = blockIdx.x * 256 + threadIdx.x;
    if (e < E0C) atomicAdd(&g_hist0[ed0[e]], 1);
    else         atomicAdd(&g_hist1[ed1[e - E0C]], 1);
}

// ---------------- 3-phase scan (both graphs fused) ----------------
__global__ void scanA_k() {
    __shared__ int red[256];
    int b = blockIdx.x, t = threadIdx.x;
    int v = (b < NB0) ? g_hist0[b * 256 + t] : g_hist1[(b - NB0) * 256 + t];
    red[t] = v; __syncthreads();
#pragma unroll
    for (int d = 128; d > 0; d >>= 1) {
        if (t < d) red[t] += red[t + d];
        __syncthreads();
    }
    if (t == 0) g_part[b] = red[0];
}

__global__ void scanB_k() {
    __shared__ int s[NBS];
    int t = threadIdx.x;
    int v = g_part[t];
    s[t] = v; __syncthreads();
#pragma unroll
    for (int d = 1; d < NBS; d <<= 1) {
        int x = (t >= d) ? s[t - d] : 0;
        __syncthreads();
        s[t] += x;
        __syncthreads();
    }
    int tot0 = s[NB0 - 1];
    int excl = s[t] - v;
    if (t >= NB0) excl -= tot0;
    g_part[t] = excl;
    if (t == 0) { g_tot0 = tot0; g_tot1 = s[NBS - 1] - tot0; }
}

__global__ void scanC_k() {
    __shared__ int s[256];
    int b = blockIdx.x, t = threadIdx.x;
    bool is0 = (b < NB0);
    int i = is0 ? b * 256 + t : (b - NB0) * 256 + t;
    int v = is0 ? g_hist0[i] : g_hist1[i];
    s[t] = v; __syncthreads();
#pragma unroll
    for (int d = 1; d < 256; d <<= 1) {
        int x = (t >= d) ? s[t - d] : 0;
        __syncthreads();
        s[t] += x;
        __syncthreads();
    }
    int off = s[t] - v + g_part[b];
    if (is0) { g_off0[i] = off; g_cur0[i] = off; }
    else     { g_off1[i] = off; g_cur1[i] = off; }
    if (t == 255) {
        if (b == NB0 - 1) g_off0[N1C] = g_tot0;
        if (b == NBS - 1) g_off1[N2C] = g_tot1;
    }
}

// ---------------- fused scatter ----------------
__global__ void scatF_k(const int* __restrict__ es0, const int* __restrict__ ed0,
                        const int* __restrict__ es1, const int* __restrict__ ed1,
                        const int* __restrict__ inode) {
    int e = blockIdx.x * 256 + threadIdx.x;
    if (e < E0C) {
        int d = ed0[e];
        int p = atomicAdd(&g_cur0[d], 1);
        g_sorted0[p] = inode[es0[e]];
    } else {
        int k = e - E0C;
        int d = ed1[k];
        int p = atomicAdd(&g_cur1[d], 1);
        g_sorted1[p] = es1[k];
    }
}

// ---------------- neighbor mean aggregation: one warp per dst ----------------
__device__ __forceinline__ void agg_body(const float* __restrict__ feat,
                                         const int* __restrict__ offs,
                                         const int* __restrict__ sorted,
                                         int n_dst, float* __restrict__ mean_out) {
    int w = (int)((blockIdx.x * (long)blockDim.x + threadIdx.x) >> 5);
    int lane = threadIdx.x & 31;
    if (w >= n_dst) return;
    int beg = offs[w], end = offs[w + 1];
    const float4* f4 = (const float4*)feat;
    float4 acc = make_float4(0.f, 0.f, 0.f, 0.f);
    for (int j = beg; j < end; j++) {
        long r = sorted[j];
        float4 v = f4[r * 32 + lane];
        acc.x += v.x; acc.y += v.y; acc.z += v.z; acc.w += v.w;
    }
    float deg = (float)(end - beg);
    float sc = 1.0f / fmaxf(deg, 1.0f);
    ((float4*)mean_out)[(long)w * 32 + lane] =
        make_float4(acc.x * sc, acc.y * sc, acc.z * sc, acc.w * sc);
}
__global__ void agg0_k(const float* __restrict__ nf) { agg_body(nf, g_off0, g_sorted0, N1C, g_mean0); }
__global__ void agg1_k() { agg_body(g_h1, g_off1, g_sorted1, N2C, g_mean1); }

// ================= mma.sync bf16-split dual-A GEMM (tensor pipe, sm_80+ PTX) =================
// out[m][n] = Aself[m]@Ws + Aneigh[m]@Wn + b (+relu layer0)
// fp32 -> bf16 hi+lo split, 3 chains/matrix: Ah*Wh + Al*Wh + Ah*Wl, fp32 HMMA accumulate.
//
// smem (dynamic, 196608 B):
//   [0)        4 W tiles [128 n][128 k] bf16, swizzled 256B rows: Wsh, Wsl, Wnh, Wnl (32768B each)
//   [131072)   4 A tiles [64 m][128 k] bf16, same layout: Ash, Asl, Anh, Anl (16384B each)
// swizzle: 16B chunk index (k>>3) XOR (row&7)  -> conflict-free ldmatrix.
#define GW_OFF 0
#define GA_OFF 131072
#define GSMEM  196608

__device__ __forceinline__ uint32_t smem_u32(const void* p) {
    uint32_t a;
    asm("{ .reg .u64 t; cvta.to.shared.u64 t, %1; cvt.u32.u64 %0, t; }" : "=r"(a) : "l"(p));
    return a;
}
__device__ __forceinline__ uint32_t swz_addr(int row, int k) {   // k = even bf16 col
    uint32_t chunk = ((uint32_t)(k >> 3)) ^ ((uint32_t)row & 7u);
    return (uint32_t)row * 256u + chunk * 16u + (uint32_t)(k & 7) * 2u;
}
__device__ __forceinline__ void split2(float a, float b, uint32_t& h, uint32_t& l) {
    __nv_bfloat16 ah = __float2bfloat16(a), bh = __float2bfloat16(b);
    float ar = a - __bfloat162float(ah);
    float br = b - __bfloat162float(bh);
    __nv_bfloat16 al = __float2bfloat16(ar), bl = __float2bfloat16(br);
    h = (uint32_t)__bfloat16_as_ushort(ah) | ((uint32_t)__bfloat16_as_ushort(bh) << 16);
    l = (uint32_t)__bfloat16_as_ushort(al) | ((uint32_t)__bfloat16_as_ushort(bl) << 16);
}
__device__ __forceinline__ void ldsm4(uint32_t* r, uint32_t addr) {
    asm volatile("ldmatrix.sync.aligned.m8n8.x4.shared.b16 {%0,%1,%2,%3}, [%4];"
                 : "=r"(r[0]), "=r"(r[1]), "=r"(r[2]), "=r"(r[3]) : "r"(addr));
}
__device__ __forceinline__ void mma16816(float* d, const uint32_t* a, uint32_t b0, uint32_t b1) {
    asm volatile("mma.sync.aligned.m16n8k16.row.col.f32.bf16.bf16.f32 "
                 "{%0,%1,%2,%3}, {%4,%5,%6,%7}, {%8,%9}, {%0,%1,%2,%3};"
                 : "+f"(d[0]), "+f"(d[1]), "+f"(d[2]), "+f"(d[3])
                 : "r"(a[0]), "r"(a[1]), "r"(a[2]), "r"(a[3]), "r"(b0), "r"(b1));
}

template <int LAYER>
__global__ void __launch_bounds__(256, 1) mgemm_k(const float* __restrict__ nf,
                                                  const int* __restrict__ inode,
                                                  const float* __restrict__ Ws,
                                                  const float* __restrict__ Wn,
                                                  const float* __restrict__ bias) {
    extern __shared__ char sm[];
    uint32_t smb = smem_u32(sm);
    int tid = threadIdx.x;
    int wid = tid >> 5;
    int lane = tid & 31;
    int m0 = blockIdx.x * 64;

    const float* __restrict__ Aself  = (LAYER == 0) ? nf : g_h1;
    const float* __restrict__ Aneigh = (LAYER == 0) ? g_mean0 : g_mean1;
    float* __restrict__ outp = (LAYER == 0) ? g_h1 : g_h2;

    // ---- W tiles: fp32 [k][n] -> bf16 hi/lo transposed [n][k], swizzled ----
    // p: mat = p>>13; q = p&8191: n = q&127, k = 2*(q>>7)  [k-pairs 0..63 -> k 0..126]
    for (int p = tid; p < 16384; p += 256) {
        int mat = p >> 13;
        int q = p & 8191;
        int n = q & 127;
        int k = (q >> 7) * 2;
        const float* W = mat ? Wn : Ws;
        float x0 = W[k * 128 + n];
        float x1 = W[(k + 1) * 128 + n];
        uint32_t h, l;
        split2(x0, x1, h, l);
        uint32_t off = swz_addr(n, k);
        char* base = sm + GW_OFF + mat * 65536;
        *(uint32_t*)(base + off) = h;            // hi tile
        *(uint32_t*)(base + 32768 + off) = l;    // lo tile
    }

    // ---- A tiles: 64 rows x 128 k, self + neigh, hi/lo ----
    {
        int r = tid >> 2;                 // local row 0..63
        int k0 = (tid & 3) * 32;          // 32 k per thread
        long selfRow = (LAYER == 0) ? (long)inode[m0 + r] : (long)(m0 + r);
        const float4* s4 = (const float4*)(Aself + selfRow * 128 + k0);
        const float4* n4 = (const float4*)(Aneigh + (long)(m0 + r) * 128 + k0);
        char* aS = sm + GA_OFF;           // Ash; +16384 Asl; +32768 Anh; +49152 Anl
#pragma unroll
        for (int q = 0; q < 8; q++) {
            float4 vs = s4[q];
            float4 vn = n4[q];
            int k = k0 + q * 4;
            uint32_t h, l;
            uint32_t o0 = swz_addr(r, k);
            uint32_t o1 = swz_addr(r, k + 2);
            split2(vs.x, vs.y, h, l);
            *(uint32_t*)(aS + o0) = h;           *(uint32_t*)(aS + 16384 + o0) = l;
            split2(vs.z, vs.w, h, l);
            *(uint32_t*)(aS + o1) = h;           *(uint32_t*)(aS + 16384 + o1) = l;
            split2(vn.x, vn.y, h, l);
            *(uint32_t*)(aS + 32768 + o0) = h;   *(uint32_t*)(aS + 49152 + o0) = l;
            split2(vn.z, vn.w, h, l);
            *(uint32_t*)(aS + 32768 + o1) = h;   *(uint32_t*)(aS + 49152 + o1) = l;
        }
    }
    __syncthreads();

    // ---- warp tiling: warp_m = wid&3 (16 rows), warp_n = wid>>2 (64 cols) ----
    int warp_m = wid & 3;
    int warp_n = wid >> 2;
    int lr = lane & 7;
    int quad = lane >> 3;

    float d[8][4];
#pragma unroll
    for (int f = 0; f < 8; f++)
#pragma unroll
        for (int j = 0; j < 4; j++) d[f][j] = 0.f;

    // ldmatrix row/col patterns (per lane)
    int arow = warp_m * 16 + (quad & 1) * 8 + lr;       // A: m row
    uint32_t abase = smb + GA_OFF + (uint32_t)arow * 256u;
    int arx = arow & 7;
    int aq = quad >> 1;                                  // chunk +0/+1

    int brow_base = warp_n * 64 + (quad >> 1) * 8 + lr;  // B: n row (plus np*16)
    int bq = quad & 1;

#pragma unroll
    for (int s = 0; s < 8; s++) {
        int kc = s * 2;                                  // base chunk = kb/8
        uint32_t ash[4], asl[4], anh[4], anl[4];
        uint32_t aoff = abase + ((uint32_t)((kc + aq) ^ arx)) * 16u;
        ldsm4(ash, aoff);
        ldsm4(asl, aoff + 16384u);
        ldsm4(anh, aoff + 32768u);
        ldsm4(anl, aoff + 49152u);
#pragma unroll
        for (int np = 0; np < 4; np++) {
            int brow = brow_base + np * 16;
            uint32_t boff = smb + GW_OFF + (uint32_t)brow * 256u +
                            ((uint32_t)((kc + bq) ^ (brow & 7))) * 16u;
            uint32_t bsh[4], bsl[4], bnh[4], bnl[4];
            ldsm4(bsh, boff);
            ldsm4(bsl, boff + 32768u);
            ldsm4(bnh, boff + 65536u);
            ldsm4(bnl, boff + 98304u);
#pragma unroll
            for (int t = 0; t < 2; t++) {
                float* dd = d[np * 2 + t];
                uint32_t b0h = bsh[2 * t], b1h = bsh[2 * t + 1];
                uint32_t b0l = bsl[2 * t], b1l = bsl[2 * t + 1];
                uint32_t n0h = bnh[2 * t], n1h = bnh[2 * t + 1];
                uint32_t n0l = bnl[2 * t], n1l = bnl[2 * t + 1];
                mma16816(dd, ash, b0h, b1h);
                mma16816(dd, asl, b0h, b1h);
                mma16816(dd, ash, b0l, b1l);
                mma16816(dd, anh, n0h, n1h);
                mma16816(dd, anl, n0h, n1h);
                mma16816(dd, anh, n0l, n1l);
            }
        }
    }

    // ---- epilogue: bias (+relu), store ----
    int group = lane >> 2;
    int col0 = warp_n * 64 + (lane & 3) * 2;
    long rowA = (long)(m0 + warp_m * 16 + group);
    long rowB = rowA + 8;
#pragma unroll
    for (int f = 0; f < 8; f++) {
        int c = col0 + f * 8;
        float bx = bias[c], by = bias[c + 1];
        float2 oA, oB;
        oA.x = d[f][0] + bx; oA.y = d[f][1] + by;
        oB.x = d[f][2] + bx; oB.y = d[f][3] + by;
        if (LAYER == 0) {
            oA.x = fmaxf(oA.x, 0.f); oA.y = fmaxf(oA.y, 0.f);
            oB.x = fmaxf(oB.x, 0.f); oB.y = fmaxf(oB.y, 0.f);
        }
        *(float2*)&outp[rowA * 128 + c] = oA;
        *(float2*)&outp[rowB * 128 + c] = oB;
    }
}

// ---------------- final pos/neg gathers ----------------
__global__ void out_k(const int* __restrict__ ps, const int* __restrict__ pd,
                      const int* __restrict__ ns, const int* __restrict__ nd,
                      float* __restrict__ out) {
    int w = (int)((blockIdx.x * (long)blockDim.x + threadIdx.x) >> 5);
    int lane = threadIdx.x & 31;
    int grp = w >> 12;
    int r = w & (PC - 1);
    const int* tab = (grp == 0) ? ps : (grp == 1) ? pd : (grp == 2) ? ns : nd;
    long src = tab[r];
    float4 v = ((const float4*)g_h2)[src * 32 + lane];
    ((float4*)out)[(long)w * 32 + lane] = v;
}

// ---------------- launch ----------------
extern "C" void kernel_launch(void* const* d_in, const int* in_sizes, int n_in,
                              void* d_out, int out_size) {
    const float* nf    = (const float*)d_in[0];
    const int*   inode = (const int*)d_in[1];
    const int*   esrc0 = (const int*)d_in[2];
    const int*   edst0 = (const int*)d_in[3];
    const int*   esrc1 = (const int*)d_in[4];
    const int*   edst1 = (const int*)d_in[5];
    const int*   ps    = (const int*)d_in[6];
    const int*   pd    = (const int*)d_in[7];
    const int*   ns    = (const int*)d_in[8];
    const int*   nd    = (const int*)d_in[9];
    const float* Ws0   = (const float*)d_in[10];
    const float* Wn0   = (const float*)d_in[11];
    const float* b0    = (const float*)d_in[12];
    const float* Ws1   = (const float*)d_in[13];
    const float* Wn1   = (const float*)d_in[14];
    const float* b1    = (const float*)d_in[15];
    float* out = (float*)d_out;

    cudaFuncSetAttribute(reinterpret_cast<const void*>(mgemm_k<0>),
                         cudaFuncAttributeMaxDynamicSharedMemorySize, GSMEM);
    cudaFuncSetAttribute(reinterpret_cast<const void*>(mgemm_k<1>),
                         cudaFuncAttributeMaxDynamicSharedMemorySize, GSMEM);

    void *p0 = nullptr, *p1 = nullptr;
    cudaGetSymbolAddress(&p0, g_hist0);
    cudaGetSymbolAddress(&p1, g_hist1);
    cudaMemsetAsync(p0, 0, N1C * sizeof(int));
    cudaMemsetAsync(p1, 0, N2C * sizeof(int));

    histF_k<<<(E0C + E1C) / 256, 256>>>(edst0, edst1);
    scanA_k<<<NBS, 256>>>();
    scanB_k<<<1, NBS>>>();
    scanC_k<<<NBS, 256>>>();
    scatF_k<<<(E0C + E1C) / 256, 256>>>(esrc0, edst0, esrc1, edst1, inode);
    agg0_k<<<(N1C * 32 + 255) / 256, 256>>>(nf);
    mgemm_k<0><<<N1C / 64, 256, GSMEM>>>(nf, inode, Ws0, Wn0, b0);
    agg1_k<<<(N2C * 32 + 255) / 256, 256>>>();
    mgemm_k<1><<<N2C / 64, 256, GSMEM>>>(nf, inode, Ws1, Wn1, b1);
    out_k<<<(4 * PC * 32) / 256, 256>>>(ps, pd, ns, nd, out);
}